// round 6
// baseline (speedup 1.0000x reference)
#include <cuda_runtime.h>

// EMA scan: fused single-kernel chunked decomposition with decaying look-back.
//   out[l,d,e] = a_e*x[l,d] + (1-a_e)*out[l-1,d,e],  out[-1,d,e] = x[0,d]
//
// CHUNK=32, oS_max = 0.9586^32 = 0.258 -> look-back J=12 terms, trunc <= 9e-8.
//
// Round-6: fuse aggr+scan into ONE kernel using device-global flags.
//   Block (k,g): stage x chunk -> smem, compute B[k] from smem, publish B +
//   flag, spin on the 12 predecessor flags, Horner carry, rescan from smem,
//   streaming stores. Deadlock-free because all 1024 blocks are co-resident:
//   __launch_bounds__(256,8) forces <=32 regs -> 8 blocks/SM -> 1184 slots.
//   Flags carry an epoch (bumped by a tiny pre-kernel) so no reset is needed
//   across graph replays.

#define LSEQ   8192
#define DFEAT  512
#define EMAS   8
#define CHUNK  32
#define NCHUNK (LSEQ / CHUNK)    // 256
#define DPB    128               // d's per block
#define NDG    (DFEAT / DPB)     // 4 d-groups
#define TPB    (DPB * 2)         // 256 threads: 2 per d (4 states each)
#define LOOKB  12
#define NST    4                 // states per thread

__device__ float g_B[NCHUNK * DFEAT * EMAS];       // 4 MB scratch
__device__ volatile int g_flag[NCHUNK * NDG];      // publish flags
__device__ int g_epoch = 0;

__global__ void bump_epoch() { ++g_epoch; }

__global__ __launch_bounds__(TPB, 8)
void ema_fused(const float* __restrict__ x,
               const float* __restrict__ log_decay,
               float* __restrict__ out)
{
    __shared__ float xs[CHUNK][DPB];   // 16 KB

    const int t  = threadIdx.x;
    const int dl = t >> 1;             // local d: 0..127
    const int e0 = (t & 1) * NST;      // 0 or 4
    const int g  = blockIdx.y;         // d-group
    const int d  = g * DPB + dl;
    const int k  = blockIdx.x;         // chunk
    const int epoch = g_epoch;

    // ---- stage x chunk into smem (coalesced float4) ----
    {
        // 32 rows x 128 floats; 256 threads, each loads float4: 2048 float4s/16KB
        // thread i loads element block: row = i/32, 4 floats at col (i%32)*4
        const float* xrow_base = x + (size_t)k * CHUNK * DFEAT + g * DPB;
        #pragma unroll
        for (int r = 0; r < CHUNK; r += 8) {           // 8 rows per pass
            int row = r + (t >> 5);                    // warp per row
            int col = (t & 31) * 4;
            float4 v = *reinterpret_cast<const float4*>(
                xrow_base + (size_t)row * DFEAT + col);
            *reinterpret_cast<float4*>(&xs[row][col]) = v;
        }
    }

    float a[NST], o[NST];
    #pragma unroll
    for (int e = 0; e < NST; ++e) {
        float la = log_decay[e0 + e];
        a[e] = 1.0f / (1.0f + expf(-la));
        o[e] = 1.0f - a[e];
    }

    __syncthreads();

    // ---- phase A: chunk aggregate B (zero carry-in), from smem ----
    float c[NST];
    #pragma unroll
    for (int e = 0; e < NST; ++e) c[e] = 0.0f;

    #pragma unroll
    for (int i = 0; i < CHUNK; ++i) {
        const float xv = xs[i][dl];
        #pragma unroll
        for (int e = 0; e < NST; ++e)
            c[e] = fmaf(o[e], c[e], a[e] * xv);
    }

    {
        float* bp = g_B + ((size_t)k * DFEAT + d) * EMAS + e0;
        *reinterpret_cast<float4*>(bp) = make_float4(c[0], c[1], c[2], c[3]);
    }
    __threadfence();
    __syncthreads();                  // all B writes of this block done
    if (t == 0) g_flag[k * NDG + g] = epoch;

    // ---- wait for the LOOKB predecessors (same d-group) ----
    const int m = (k < LOOKB) ? k : LOOKB;
    if (t < m) {                      // lane t polls flag of chunk k-1-t
        while (g_flag[(k - 1 - t) * NDG + g] < epoch) { }
    }
    __syncthreads();
    __threadfence();                  // acquire side

    // ---- carry via Horner: acc = B[k-1] + oS*(B[k-2] + ... ( + oS*x0)) ----
    float oS[NST];
    #pragma unroll
    for (int e = 0; e < NST; ++e) {
        float tmp = o[e];
        #pragma unroll
        for (int s = 0; s < 5; ++s) tmp *= tmp;   // o^32
        oS[e] = tmp;
    }

    #pragma unroll
    for (int e = 0; e < NST; ++e) c[e] = 0.0f;
    if (k <= LOOKB) {
        const float x0 = x[d];        // exact initial-condition seed
        #pragma unroll
        for (int e = 0; e < NST; ++e) c[e] = x0;
    }
    for (int j = m; j >= 1; --j) {    // oldest -> newest
        const float* bp = g_B + ((size_t)(k - j) * DFEAT + d) * EMAS + e0;
        const float4 bv = *reinterpret_cast<const float4*>(bp);
        c[0] = fmaf(oS[0], c[0], bv.x);
        c[1] = fmaf(oS[1], c[1], bv.y);
        c[2] = fmaf(oS[2], c[2], bv.z);
        c[3] = fmaf(oS[3], c[3], bv.w);
    }

    // ---- phase B: rescan from smem with carry, streaming stores ----
    float* op = out + ((size_t)k * CHUNK * DFEAT + d) * EMAS + e0;
    #pragma unroll
    for (int i = 0; i < CHUNK; ++i) {
        const float xv = xs[i][dl];
        #pragma unroll
        for (int e = 0; e < NST; ++e)
            c[e] = fmaf(o[e], c[e], a[e] * xv);
        __stcs(reinterpret_cast<float4*>(op + (size_t)i * (DFEAT * EMAS)),
               make_float4(c[0], c[1], c[2], c[3]));
    }
}

extern "C" void kernel_launch(void* const* d_in, const int* in_sizes, int n_in,
                              void* d_out, int out_size)
{
    const float* x  = (const float*)d_in[0];
    const float* ld = (const float*)d_in[1];
    if (n_in >= 2 && in_sizes[0] == EMAS && in_sizes[1] == LSEQ * DFEAT) {
        x  = (const float*)d_in[1];
        ld = (const float*)d_in[0];
    }
    float* out = (float*)d_out;

    bump_epoch<<<1, 1>>>();
    dim3 grid(NCHUNK, NDG);   // (256, 4) = 1024 blocks, all co-resident
    ema_fused<<<grid, TPB>>>(x, ld, out);
}

// round 7
// speedup vs baseline: 1.1041x; 1.1041x over previous
#include <cuda_runtime.h>

// EMA scan via chunked decomposition with decaying look-back (no serial pass).
//   out[l,d,e] = a_e*x[l,d] + (1-a_e)*out[l-1,d,e],  out[-1,d,e] = x[0,d]
//
// CHUNK=32, oS_max = 0.9586^32 = 0.258 -> look-back J=12 terms, trunc <= 9e-8.
//
// Round-7: back to 2 kernels (no flags). Both kernels stage the x chunk into
// smem with 4 coalesced LDG.128/thread (front-batched), then run the scan off
// 29-cycle LDS broadcasts. This removes the per-step global-load latency AND
// the xv[] register batch, so __launch_bounds__(256,8) (<=32 regs) holds with
// full memory parallelism: 8 blocks/SM -> grid 1024 fits in ONE wave.

#define LSEQ   8192
#define DFEAT  512
#define EMAS   8
#define CHUNK  32
#define NCHUNK (LSEQ / CHUNK)    // 256
#define DPB    128               // d's per block
#define NDG    (DFEAT / DPB)     // 4
#define TPB    (DPB * 2)         // 256 threads: 2 per d (4 states each)
#define LOOKB  12
#define NST    4                 // states per thread

__device__ float g_B[NCHUNK * DFEAT * EMAS];   // 4 MB scratch

// stage one (CHUNK x DPB) x-tile into smem, fully coalesced float4
__device__ __forceinline__ void stage_x(const float* __restrict__ x,
                                        int k, int g, int t,
                                        float (*xs)[DPB])
{
    const float* base = x + (size_t)k * CHUNK * DFEAT + g * DPB;
    float4 v[4];
    #pragma unroll
    for (int p = 0; p < 4; ++p) {                 // front-batched: MLP=4
        int i   = t + TPB * p;                    // float4 index 0..1023
        int row = i >> 5;
        int col = (i & 31) * 4;
        v[p] = *reinterpret_cast<const float4*>(base + (size_t)row * DFEAT + col);
    }
    #pragma unroll
    for (int p = 0; p < 4; ++p) {
        int i   = t + TPB * p;
        int row = i >> 5;
        int col = (i & 31) * 4;
        *reinterpret_cast<float4*>(&xs[row][col]) = v[p];
    }
}

__device__ __forceinline__ void load_coeffs4(const float* __restrict__ log_decay,
                                             int e0, float* a, float* o)
{
    #pragma unroll
    for (int e = 0; e < NST; ++e) {
        float la = __ldg(log_decay + e0 + e);
        a[e] = 1.0f / (1.0f + expf(-la));
        o[e] = 1.0f - a[e];
    }
}

// ---- Kernel 1: per-chunk aggregates (zero carry-in) ----
__global__ __launch_bounds__(TPB, 8)
void ema_aggr(const float* __restrict__ x,
              const float* __restrict__ log_decay)
{
    __shared__ float xs[CHUNK][DPB];
    const int t  = threadIdx.x;
    const int dl = t >> 1;
    const int e0 = (t & 1) * NST;
    const int g  = blockIdx.y;
    const int d  = g * DPB + dl;
    const int k  = blockIdx.x;

    stage_x(x, k, g, t, xs);

    float a[NST], o[NST];
    load_coeffs4(log_decay, e0, a, o);
    __syncthreads();

    float B[NST];
    #pragma unroll
    for (int e = 0; e < NST; ++e) B[e] = 0.0f;

    #pragma unroll
    for (int i = 0; i < CHUNK; ++i) {
        const float xv = xs[i][dl];
        #pragma unroll
        for (int e = 0; e < NST; ++e)
            B[e] = fmaf(o[e], B[e], a[e] * xv);
    }

    float* bp = g_B + ((size_t)k * DFEAT + d) * EMAS + e0;
    *reinterpret_cast<float4*>(bp) = make_float4(B[0], B[1], B[2], B[3]);
}

// ---- Kernel 2: look-back carry, then scan + store ----
__global__ __launch_bounds__(TPB, 8)
void ema_scan(const float* __restrict__ x,
              const float* __restrict__ log_decay,
              float* __restrict__ out)
{
    __shared__ float xs[CHUNK][DPB];
    const int t  = threadIdx.x;
    const int dl = t >> 1;
    const int e0 = (t & 1) * NST;
    const int g  = blockIdx.y;
    const int d  = g * DPB + dl;
    const int k  = blockIdx.x;

    stage_x(x, k, g, t, xs);

    float a[NST], o[NST];
    load_coeffs4(log_decay, e0, a, o);

    // oS = o^CHUNK = o^32
    float oS[NST];
    #pragma unroll
    for (int e = 0; e < NST; ++e) {
        float tmp = o[e];
        #pragma unroll
        for (int s = 0; s < 5; ++s) tmp *= tmp;
        oS[e] = tmp;
    }

    // carry via Horner over the last min(k,LOOKB) chunk aggregates
    // (exact x0 seed when k <= LOOKB)
    const int m = (k < LOOKB) ? k : LOOKB;
    float c[NST];
    #pragma unroll
    for (int e = 0; e < NST; ++e) c[e] = 0.0f;
    if (k <= LOOKB) {
        const float x0 = __ldg(x + d);
        #pragma unroll
        for (int e = 0; e < NST; ++e) c[e] = x0;
    }
    for (int j = m; j >= 1; --j) {    // oldest -> newest
        const float* bp = g_B + ((size_t)(k - j) * DFEAT + d) * EMAS + e0;
        const float4 bv = *reinterpret_cast<const float4*>(bp);
        c[0] = fmaf(oS[0], c[0], bv.x);
        c[1] = fmaf(oS[1], c[1], bv.y);
        c[2] = fmaf(oS[2], c[2], bv.z);
        c[3] = fmaf(oS[3], c[3], bv.w);
    }

    __syncthreads();

    // scan this chunk from smem, streaming stores
    float* op = out + ((size_t)k * CHUNK * DFEAT + d) * EMAS + e0;
    #pragma unroll
    for (int i = 0; i < CHUNK; ++i) {
        const float xv = xs[i][dl];
        #pragma unroll
        for (int e = 0; e < NST; ++e)
            c[e] = fmaf(o[e], c[e], a[e] * xv);
        __stcs(reinterpret_cast<float4*>(op + (size_t)i * (DFEAT * EMAS)),
               make_float4(c[0], c[1], c[2], c[3]));
    }
}

extern "C" void kernel_launch(void* const* d_in, const int* in_sizes, int n_in,
                              void* d_out, int out_size)
{
    const float* x  = (const float*)d_in[0];
    const float* ld = (const float*)d_in[1];
    if (n_in >= 2 && in_sizes[0] == EMAS && in_sizes[1] == LSEQ * DFEAT) {
        x  = (const float*)d_in[1];
        ld = (const float*)d_in[0];
    }
    float* out = (float*)d_out;

    dim3 grid(NCHUNK, NDG);   // (256, 4) = 1024 blocks; one wave at 8/SM
    ema_aggr<<<grid, TPB>>>(x, ld);
    ema_scan<<<grid, TPB>>>(x, ld, out);
}